// round 8
// baseline (speedup 1.0000x reference)
#include <cuda_runtime.h>
#include <cuda_bf16.h>

// Problem constants
#define N_WORKER   1807
#define N_PROJECT  2490
#define EMB        10
#define STATE_DIM  20
#define HIDDEN     40
#define NCAND      2489        // candidates = project_emb rows 1..2489 (cand c -> row c+1)
#define BATCH      65536

#define NSPLIT     2
#define SPLIT_CAND 1248        // candidates per split (2*1248 = 2496 >= 2489, NaN pad)
#define CHUNK      312         // candidates staged per pass (312*10 u64 = 24960 B)
#define NCHUNK     4
#define THREADS    128
#define SPT        4           // samples per thread in actor
#define SBLK       (BATCH / (THREADS * SPT))   // 128 sample blocks
#define ACTOR_CTAS (SBLK * NSPLIT)             // 256 -> single wave on 148 SMs

// runtime-detected layout flags
__device__ int g_swap_ids;     // 1 => idA is project_ids
__device__ int g_ids64;        // 1 => id arrays are int64

// per-sample action weights (plain floats; actor packs sample-pairs)
__device__ float g_w[BATCH][EMB];
// per-split packed partial argmax: (val, idx-bits) in one u64
__device__ unsigned long long g_pack[NSPLIT][BATCH];

// ---- packed f32x2 helpers (sm_103a FFMA2 path) ----
__device__ __forceinline__ unsigned long long pack2(float lo, float hi) {
    unsigned long long r;
    asm("mov.b64 %0, {%1, %2};" : "=l"(r) : "f"(lo), "f"(hi));
    return r;
}
__device__ __forceinline__ void unpack2(unsigned long long v, float& lo, float& hi) {
    asm("mov.b64 {%0, %1}, %2;" : "=f"(lo), "=f"(hi) : "l"(v));
}
__device__ __forceinline__ unsigned long long fmul2(unsigned long long a, unsigned long long b) {
    unsigned long long d;
    asm("mul.rn.f32x2 %0, %1, %2;" : "=l"(d) : "l"(a), "l"(b));
    return d;
}
__device__ __forceinline__ unsigned long long ffma2(unsigned long long a, unsigned long long b,
                                                    unsigned long long c) {
    unsigned long long d;
    asm("fma.rn.f32x2 %0, %1, %2, %3;" : "=l"(d) : "l"(a), "l"(b), "l"(c));
    return d;
}

// ---- pre-pass (sampled): id dtype + which array is project_ids ----
__global__ void detect_kernel(const unsigned int* __restrict__ idA,
                              const unsigned int* __restrict__ idB)
{
    __shared__ unsigned int s_or[8];
    __shared__ unsigned int s_mx[8];
    unsigned int odd_or = 0, even_mx = 0;
    for (int i = threadIdx.x; i < BATCH / 2; i += 256 * 16) {   // 8 iters/thread
        odd_or  |= idA[2 * i + 1] | idB[2 * i + 1];
        even_mx  = max(even_mx, idA[2 * i]);
    }
    #pragma unroll
    for (int o = 16; o > 0; o >>= 1) {
        odd_or  |= __shfl_xor_sync(0xffffffffu, odd_or, o);
        even_mx  = max(even_mx, __shfl_xor_sync(0xffffffffu, even_mx, o));
    }
    if ((threadIdx.x & 31) == 0) {
        s_or[threadIdx.x >> 5] = odd_or;
        s_mx[threadIdx.x >> 5] = even_mx;
    }
    __syncthreads();
    if (threadIdx.x == 0) {
        unsigned int oo = 0, mm = 0;
        #pragma unroll
        for (int w = 0; w < 8; w++) { oo |= s_or[w]; mm = max(mm, s_mx[w]); }
        g_ids64    = (oo == 0) ? 1 : 0;
        g_swap_ids = (mm >= (unsigned)N_WORKER) ? 1 : 0;
    }
}

__device__ __forceinline__ int load_id(const void* p, int i, int ids64) {
    return ids64 ? (int)((const long long*)p)[i] : ((const int*)p)[i];
}

// ---- MLP kernel: one sample per thread, plain float action weights ----
__global__ __launch_bounds__(256)
void mlp_kernel(const void* __restrict__ idA,
                const void* __restrict__ idB,
                const float* __restrict__ worker_emb,
                const float* __restrict__ project_emb,
                const float* __restrict__ W1,
                const float* __restrict__ b1,
                const float* __restrict__ W2,
                const float* __restrict__ b2)
{
    __shared__ float sW1[HIDDEN * STATE_DIM];
    __shared__ float sb1[HIDDEN];
    __shared__ float sW2[EMB * HIDDEN];
    __shared__ float sb2[EMB];

    const int tid = threadIdx.x;
    for (int i = tid; i < HIDDEN * STATE_DIM; i += 256) sW1[i] = W1[i];
    for (int i = tid; i < EMB * HIDDEN; i += 256)       sW2[i] = W2[i];
    if (tid < HIDDEN) sb1[tid] = b1[tid];
    if (tid < EMB)    sb2[tid] = b2[tid];

    const int swap  = g_swap_ids;
    const int ids64 = g_ids64;
    const void* worker_ids  = swap ? idB : idA;
    const void* project_ids = swap ? idA : idB;
    __syncthreads();

    const int g  = blockIdx.x * 256 + tid;
    const int wi = load_id(worker_ids,  g, ids64);
    const int pi = load_id(project_ids, g, ids64);

    float x[STATE_DIM];
    const float* wrow = worker_emb + wi * EMB;
    const float* prow = project_emb + pi * EMB;
    #pragma unroll
    for (int j = 0; j < EMB; j++) x[j] = __ldg(wrow + j);
    #pragma unroll
    for (int j = 0; j < EMB; j++) x[EMB + j] = __ldg(prow + j);

    float a[EMB];
    #pragma unroll
    for (int d = 0; d < EMB; d++) a[d] = sb2[d];

    #pragma unroll 2
    for (int k = 0; k < HIDDEN; k++) {
        float hk = sb1[k];
        #pragma unroll
        for (int j = 0; j < STATE_DIM; j++) hk += sW1[k * STATE_DIM + j] * x[j];
        hk = fmaxf(hk, 0.0f);
        #pragma unroll
        for (int d = 0; d < EMB; d++) a[d] += sW2[d * HIDDEN + k] * hk;
    }
    // g_w row is 40B -> 8-byte aligned: 5 STG.64
    float2* wrow_out = reinterpret_cast<float2*>(g_w[g]);
    #pragma unroll
    for (int j = 0; j < 5; j++) wrow_out[j] = make_float2(a[2 * j], a[2 * j + 1]);
}

// ---- actor: SAMPLE-pair packed dots; 4 samples/thread; 1 argmax stream each ----
__global__ __launch_bounds__(THREADS)
void actor_kernel(const float* __restrict__ project_emb)
{
    // duplicated-pair table: tbl[c*10 + j] = (t_c[j], t_c[j])
    __shared__ __align__(16) unsigned long long tbl[CHUNK * EMB];   // 24960 B

    const int split = blockIdx.x & (NSPLIT - 1);
    const int sblk  = blockIdx.x >> 1;
    const int c0    = split * SPLIT_CAND;
    const int tid   = threadIdx.x;

    // per-thread: 4 samples -> 2 sample-pair packed weight vectors (40 regs)
    int g[SPT];
    unsigned long long wd01[EMB], wd23[EMB];
    {
        float aw[SPT][EMB];
        #pragma unroll
        for (int s = 0; s < SPT; s++) {
            g[s] = (sblk * SPT + s) * THREADS + tid;
            const float2* wr = reinterpret_cast<const float2*>(g_w[g[s]]);
            #pragma unroll
            for (int j = 0; j < 5; j++) {
                const float2 v = __ldg(wr + j);
                aw[s][2 * j] = v.x; aw[s][2 * j + 1] = v.y;
            }
        }
        #pragma unroll
        for (int j = 0; j < EMB; j++) {
            wd01[j] = pack2(aw[0][j], aw[1][j]);
            wd23[j] = pack2(aw[2][j], aw[3][j]);
        }
    }

    float bv[SPT];
    int   bc[SPT];
    #pragma unroll
    for (int s = 0; s < SPT; s++) { bv[s] = __int_as_float(0xff800000); bc[s] = 0; }

    for (int chunk = 0; chunk < NCHUNK; chunk++) {
        const int cc0 = c0 + chunk * CHUNK;     // global candidate base of chunk
        __syncthreads();   // previous chunk's readers done before overwrite
        // stage duplicated pairs; NaN pad beyond NCAND (NaN never wins '>')
        for (int e = tid; e < CHUNK * EMB; e += THREADS) {
            const int c = e / EMB;
            const int j = e - c * EMB;
            const int ci = cc0 + c;
            const float t = (ci < NCAND) ? __ldg(project_emb + (ci + 1) * EMB + j)
                                         : __int_as_float(0x7fffffff);
            tbl[e] = pack2(t, t);
        }
        __syncthreads();

        const ulonglong2* q = reinterpret_cast<const ulonglong2*>(tbl);
        #pragma unroll 2
        for (int c = 0; c < CHUNK; c++) {
            const ulonglong2 q0 = q[c * 5 + 0];   // dims 0,1 (each duplicated)
            const ulonglong2 q1 = q[c * 5 + 1];   // dims 2,3
            const ulonglong2 q2 = q[c * 5 + 2];   // dims 4,5
            const ulonglong2 q3 = q[c * 5 + 3];   // dims 6,7
            const ulonglong2 q4 = q[c * 5 + 4];   // dims 8,9

            unsigned long long a01 = fmul2(wd01[0], q0.x);
            unsigned long long a23 = fmul2(wd23[0], q0.x);
            a01 = ffma2(wd01[1], q0.y, a01);  a23 = ffma2(wd23[1], q0.y, a23);
            a01 = ffma2(wd01[2], q1.x, a01);  a23 = ffma2(wd23[2], q1.x, a23);
            a01 = ffma2(wd01[3], q1.y, a01);  a23 = ffma2(wd23[3], q1.y, a23);
            a01 = ffma2(wd01[4], q2.x, a01);  a23 = ffma2(wd23[4], q2.x, a23);
            a01 = ffma2(wd01[5], q2.y, a01);  a23 = ffma2(wd23[5], q2.y, a23);
            a01 = ffma2(wd01[6], q3.x, a01);  a23 = ffma2(wd23[6], q3.x, a23);
            a01 = ffma2(wd01[7], q3.y, a01);  a23 = ffma2(wd23[7], q3.y, a23);
            a01 = ffma2(wd01[8], q4.x, a01);  a23 = ffma2(wd23[8], q4.x, a23);
            a01 = ffma2(wd01[9], q4.y, a01);  a23 = ffma2(wd23[9], q4.y, a23);

            float d[SPT];
            unpack2(a01, d[0], d[1]);
            unpack2(a23, d[2], d[3]);
            const int ci = cc0 + c;
            #pragma unroll
            for (int s = 0; s < SPT; s++) {
                const bool gt = (d[s] > bv[s]);   // ascending ci + strict '>' = first max
                bv[s] = gt ? d[s] : bv[s];
                bc[s] = gt ? ci   : bc[s];
            }
        }
    }

    #pragma unroll
    for (int s = 0; s < SPT; s++)
        g_pack[split][g[s]] = pack2(bv[s], __int_as_float(bc[s]));
}

// ---- merge the 2 splits; split1 indices all larger: strict '>' keeps first ----
__global__ void merge_kernel(float* __restrict__ out)
{
    const int i = blockIdx.x * 256 + threadIdx.x;
    float v0, i0f, v1, i1f;
    unpack2(g_pack[0][i], v0, i0f);
    unpack2(g_pack[1][i], v1, i1f);
    const int ix = (v1 > v0) ? __float_as_int(i1f) : __float_as_int(i0f);
    out[i] = (float)(ix + 1);
}

extern "C" void kernel_launch(void* const* d_in, const int* in_sizes, int n_in,
                              void* d_out, int out_size)
{
    // Order-proof binding: every float array has a unique element count.
    const void*  idA = nullptr;
    const void*  idB = nullptr;
    const float* worker_emb  = nullptr;  // 18070
    const float* project_emb = nullptr;  // 24900
    const float* W1 = nullptr;           // 800
    const float* b1 = nullptr;           // 40
    const float* W2 = nullptr;           // 400
    const float* b2 = nullptr;           // 10

    for (int i = 0; i < n_in; i++) {
        switch (in_sizes[i]) {
            case BATCH: if (!idA) idA = d_in[i];
                        else      idB = d_in[i];                      break;
            case 18070: worker_emb  = (const float*)d_in[i];          break;
            case 24900: project_emb = (const float*)d_in[i];          break;
            case 800:   W1 = (const float*)d_in[i];                   break;
            case 40:    b1 = (const float*)d_in[i];                   break;
            case 400:   W2 = (const float*)d_in[i];                   break;
            case 10:    b2 = (const float*)d_in[i];                   break;
            default: break;
        }
    }

    detect_kernel<<<1, 256>>>((const unsigned int*)idA, (const unsigned int*)idB);
    mlp_kernel<<<BATCH / 256, 256>>>(idA, idB, worker_emb, project_emb,
                                     W1, b1, W2, b2);
    actor_kernel<<<ACTOR_CTAS, THREADS>>>(project_emb);
    merge_kernel<<<BATCH / 256, 256>>>((float*)d_out);
}

// round 9
// speedup vs baseline: 1.1729x; 1.1729x over previous
#include <cuda_runtime.h>
#include <cuda_bf16.h>

// Problem constants
#define N_WORKER   1807
#define N_PROJECT  2490
#define EMB        10
#define STATE_DIM  20
#define HIDDEN     40
#define NCAND      2489        // candidates = project_emb rows 1..2489 (cand c -> row c+1)
#define BATCH      65536

#define NSPLIT     8
#define SPLIT_CAND 312         // candidates per split (8*312 = 2496 >= 2489, NaN pad)
#define THREADS    128
#define SPT        4           // samples per thread in actor
#define SBLK       (BATCH / (THREADS * SPT))   // 128 sample blocks
#define ACTOR_CTAS (SBLK * NSPLIT)             // 1024 CTAs, 4/SM resident -> 16 warps/SM

// runtime-detected layout flags
__device__ int g_swap_ids;     // 1 => idA is project_ids
__device__ int g_ids64;        // 1 => id arrays are int64

// per-sample action weights (plain floats; actor packs sample-pairs)
__device__ float g_w[BATCH][EMB];
// per-split packed partial argmax: (val, idx-bits) in one u64
__device__ unsigned long long g_pack[NSPLIT][BATCH];

// ---- packed f32x2 helpers (sm_103a FFMA2 path) ----
__device__ __forceinline__ unsigned long long pack2(float lo, float hi) {
    unsigned long long r;
    asm("mov.b64 %0, {%1, %2};" : "=l"(r) : "f"(lo), "f"(hi));
    return r;
}
__device__ __forceinline__ void unpack2(unsigned long long v, float& lo, float& hi) {
    asm("mov.b64 {%0, %1}, %2;" : "=f"(lo), "=f"(hi) : "l"(v));
}
__device__ __forceinline__ unsigned long long fmul2(unsigned long long a, unsigned long long b) {
    unsigned long long d;
    asm("mul.rn.f32x2 %0, %1, %2;" : "=l"(d) : "l"(a), "l"(b));
    return d;
}
__device__ __forceinline__ unsigned long long ffma2(unsigned long long a, unsigned long long b,
                                                    unsigned long long c) {
    unsigned long long d;
    asm("fma.rn.f32x2 %0, %1, %2, %3;" : "=l"(d) : "l"(a), "l"(b), "l"(c));
    return d;
}

// ---- pre-pass (tiny sample): id dtype + which array is project_ids ----
// 256 u64-slots per array. int32 ids: odd words are real ids, all-zero whp impossible.
// swap: P[no project id >= 1807 in 256 samples] = (1807/2490)^256 ~ e^-82.
__global__ void detect_kernel(const unsigned int* __restrict__ idA,
                              const unsigned int* __restrict__ idB)
{
    __shared__ unsigned int s_or[8];
    __shared__ unsigned int s_mx[8];
    const int i = threadIdx.x * (BATCH / 512);     // stride 128 u32 slots
    unsigned int odd_or = idA[2 * i + 1] | idB[2 * i + 1];
    unsigned int even_mx = idA[2 * i];
    #pragma unroll
    for (int o = 16; o > 0; o >>= 1) {
        odd_or  |= __shfl_xor_sync(0xffffffffu, odd_or, o);
        even_mx  = max(even_mx, __shfl_xor_sync(0xffffffffu, even_mx, o));
    }
    if ((threadIdx.x & 31) == 0) {
        s_or[threadIdx.x >> 5] = odd_or;
        s_mx[threadIdx.x >> 5] = even_mx;
    }
    __syncthreads();
    if (threadIdx.x == 0) {
        unsigned int oo = 0, mm = 0;
        #pragma unroll
        for (int w = 0; w < 8; w++) { oo |= s_or[w]; mm = max(mm, s_mx[w]); }
        g_ids64    = (oo == 0) ? 1 : 0;
        g_swap_ids = (mm >= (unsigned)N_WORKER) ? 1 : 0;
    }
}

__device__ __forceinline__ int load_id(const void* p, int i, int ids64) {
    return ids64 ? (int)((const long long*)p)[i] : ((const int*)p)[i];
}

// ---- MLP kernel: one sample per thread, plain float action weights ----
__global__ __launch_bounds__(256)
void mlp_kernel(const void* __restrict__ idA,
                const void* __restrict__ idB,
                const float* __restrict__ worker_emb,
                const float* __restrict__ project_emb,
                const float* __restrict__ W1,
                const float* __restrict__ b1,
                const float* __restrict__ W2,
                const float* __restrict__ b2)
{
    __shared__ float sW1[HIDDEN * STATE_DIM];
    __shared__ float sb1[HIDDEN];
    __shared__ float sW2[EMB * HIDDEN];
    __shared__ float sb2[EMB];

    const int tid = threadIdx.x;
    for (int i = tid; i < HIDDEN * STATE_DIM; i += 256) sW1[i] = W1[i];
    for (int i = tid; i < EMB * HIDDEN; i += 256)       sW2[i] = W2[i];
    if (tid < HIDDEN) sb1[tid] = b1[tid];
    if (tid < EMB)    sb2[tid] = b2[tid];

    const int swap  = g_swap_ids;
    const int ids64 = g_ids64;
    const void* worker_ids  = swap ? idB : idA;
    const void* project_ids = swap ? idA : idB;
    __syncthreads();

    const int g  = blockIdx.x * 256 + tid;
    const int wi = load_id(worker_ids,  g, ids64);
    const int pi = load_id(project_ids, g, ids64);

    float x[STATE_DIM];
    const float* wrow = worker_emb + wi * EMB;
    const float* prow = project_emb + pi * EMB;
    #pragma unroll
    for (int j = 0; j < EMB; j++) x[j] = __ldg(wrow + j);
    #pragma unroll
    for (int j = 0; j < EMB; j++) x[EMB + j] = __ldg(prow + j);

    float a[EMB];
    #pragma unroll
    for (int d = 0; d < EMB; d++) a[d] = sb2[d];

    #pragma unroll 2
    for (int k = 0; k < HIDDEN; k++) {
        float hk = sb1[k];
        #pragma unroll
        for (int j = 0; j < STATE_DIM; j++) hk += sW1[k * STATE_DIM + j] * x[j];
        hk = fmaxf(hk, 0.0f);
        #pragma unroll
        for (int d = 0; d < EMB; d++) a[d] += sW2[d * HIDDEN + k] * hk;
    }
    // g_w row is 40B -> 8-byte aligned: 5 STG.64
    float2* wrow_out = reinterpret_cast<float2*>(g_w[g]);
    #pragma unroll
    for (int j = 0; j < 5; j++) wrow_out[j] = make_float2(a[2 * j], a[2 * j + 1]);
}

// ---- actor: sample-pair packed dots; 4 samples/thread; 16 warps/SM ----
__global__ __launch_bounds__(THREADS, 4)
void actor_kernel(const float* __restrict__ project_emb)
{
    // duplicated-pair table: tbl[c*10 + j] = (t_c[j], t_c[j]); 24960 B
    __shared__ __align__(16) unsigned long long tbl[SPLIT_CAND * EMB];

    const int split = blockIdx.x & (NSPLIT - 1);
    const int sblk  = blockIdx.x >> 3;
    const int c0    = split * SPLIT_CAND;     // global candidate base
    const int tid   = threadIdx.x;

    // stage duplicated pairs; NaN pad beyond NCAND (NaN never wins '>')
    for (int e = tid; e < SPLIT_CAND * EMB; e += THREADS) {
        const int c = e / EMB;
        const int j = e - c * EMB;
        const int ci = c0 + c;
        const float t = (ci < NCAND) ? __ldg(project_emb + (ci + 1) * EMB + j)
                                     : __int_as_float(0x7fffffff);
        tbl[e] = pack2(t, t);
    }

    // per-thread: 4 samples -> 2 sample-pair packed weight vectors (40 regs)
    int g[SPT];
    unsigned long long wd01[EMB], wd23[EMB];
    {
        float aw[SPT][EMB];
        #pragma unroll
        for (int s = 0; s < SPT; s++) {
            g[s] = (sblk * SPT + s) * THREADS + tid;
            const float2* wr = reinterpret_cast<const float2*>(g_w[g[s]]);
            #pragma unroll
            for (int j = 0; j < 5; j++) {
                const float2 v = __ldg(wr + j);
                aw[s][2 * j] = v.x; aw[s][2 * j + 1] = v.y;
            }
        }
        #pragma unroll
        for (int j = 0; j < EMB; j++) {
            wd01[j] = pack2(aw[0][j], aw[1][j]);
            wd23[j] = pack2(aw[2][j], aw[3][j]);
        }
    }
    __syncthreads();

    float bv[SPT];
    int   bc[SPT];
    #pragma unroll
    for (int s = 0; s < SPT; s++) { bv[s] = __int_as_float(0xff800000); bc[s] = 0; }

    const ulonglong2* q = reinterpret_cast<const ulonglong2*>(tbl);
    #pragma unroll 2
    for (int c = 0; c < SPLIT_CAND; c++) {
        const ulonglong2 q0 = q[c * 5 + 0];   // dims 0,1 (each duplicated)
        const ulonglong2 q1 = q[c * 5 + 1];   // dims 2,3
        const ulonglong2 q2 = q[c * 5 + 2];   // dims 4,5
        const ulonglong2 q3 = q[c * 5 + 3];   // dims 6,7
        const ulonglong2 q4 = q[c * 5 + 4];   // dims 8,9

        unsigned long long a01 = fmul2(wd01[0], q0.x);
        unsigned long long a23 = fmul2(wd23[0], q0.x);
        a01 = ffma2(wd01[1], q0.y, a01);  a23 = ffma2(wd23[1], q0.y, a23);
        a01 = ffma2(wd01[2], q1.x, a01);  a23 = ffma2(wd23[2], q1.x, a23);
        a01 = ffma2(wd01[3], q1.y, a01);  a23 = ffma2(wd23[3], q1.y, a23);
        a01 = ffma2(wd01[4], q2.x, a01);  a23 = ffma2(wd23[4], q2.x, a23);
        a01 = ffma2(wd01[5], q2.y, a01);  a23 = ffma2(wd23[5], q2.y, a23);
        a01 = ffma2(wd01[6], q3.x, a01);  a23 = ffma2(wd23[6], q3.x, a23);
        a01 = ffma2(wd01[7], q3.y, a01);  a23 = ffma2(wd23[7], q3.y, a23);
        a01 = ffma2(wd01[8], q4.x, a01);  a23 = ffma2(wd23[8], q4.x, a23);
        a01 = ffma2(wd01[9], q4.y, a01);  a23 = ffma2(wd23[9], q4.y, a23);

        float d[SPT];
        unpack2(a01, d[0], d[1]);
        unpack2(a23, d[2], d[3]);
        #pragma unroll
        for (int s = 0; s < SPT; s++) {
            const bool gt = (d[s] > bv[s]);   // ascending c + strict '>' = first max
            bv[s] = gt ? d[s] : bv[s];
            bc[s] = gt ? c    : bc[s];
        }
    }

    #pragma unroll
    for (int s = 0; s < SPT; s++)
        g_pack[split][g[s]] = pack2(bv[s], __int_as_float(c0 + bc[s]));
}

// ---- merge the 8 splits; splits ascend in index: strict '>' keeps first max ----
__global__ void merge_kernel(float* __restrict__ out)
{
    const int i = blockIdx.x * 256 + threadIdx.x;
    float v, ixf;
    unpack2(g_pack[0][i], v, ixf);
    #pragma unroll
    for (int s = 1; s < NSPLIT; s++) {
        float vs, ixs;
        unpack2(g_pack[s][i], vs, ixs);
        const bool t = (vs > v);
        v   = t ? vs  : v;
        ixf = t ? ixs : ixf;
    }
    out[i] = (float)(__float_as_int(ixf) + 1);
}

extern "C" void kernel_launch(void* const* d_in, const int* in_sizes, int n_in,
                              void* d_out, int out_size)
{
    // Order-proof binding: every float array has a unique element count.
    const void*  idA = nullptr;
    const void*  idB = nullptr;
    const float* worker_emb  = nullptr;  // 18070
    const float* project_emb = nullptr;  // 24900
    const float* W1 = nullptr;           // 800
    const float* b1 = nullptr;           // 40
    const float* W2 = nullptr;           // 400
    const float* b2 = nullptr;           // 10

    for (int i = 0; i < n_in; i++) {
        switch (in_sizes[i]) {
            case BATCH: if (!idA) idA = d_in[i];
                        else      idB = d_in[i];                      break;
            case 18070: worker_emb  = (const float*)d_in[i];          break;
            case 24900: project_emb = (const float*)d_in[i];          break;
            case 800:   W1 = (const float*)d_in[i];                   break;
            case 40:    b1 = (const float*)d_in[i];                   break;
            case 400:   W2 = (const float*)d_in[i];                   break;
            case 10:    b2 = (const float*)d_in[i];                   break;
            default: break;
        }
    }

    detect_kernel<<<1, 256>>>((const unsigned int*)idA, (const unsigned int*)idB);
    mlp_kernel<<<BATCH / 256, 256>>>(idA, idB, worker_emb, project_emb,
                                     W1, b1, W2, b2);
    actor_kernel<<<ACTOR_CTAS, THREADS>>>(project_emb);
    merge_kernel<<<BATCH / 256, 256>>>((float*)d_out);
}

// round 10
// speedup vs baseline: 1.1946x; 1.0185x over previous
#include <cuda_runtime.h>
#include <cuda_bf16.h>

// Problem constants
#define N_WORKER   1807
#define N_PROJECT  2490
#define EMB        10
#define STATE_DIM  20
#define HIDDEN     40
#define NCAND      2489        // candidates = project_emb rows 1..2489 (cand c -> row c+1)
#define BATCH      65536

#define NSPLIT     13
#define SPLIT_CAND 192         // 13*192 = 2496 >= 2489, NaN pad
#define THREADS    128
#define SPT        4           // samples per thread in actor
#define SBLK       (BATCH / (THREADS * SPT))   // 128 sample blocks
#define ACTOR_CTAS (SBLK * NSPLIT)             // 1664 CTAs -> 2.81 waves @4/SM (93.7% tail)

// per-sample action weights (plain floats; actor packs sample-pairs)
__device__ float g_w[BATCH][EMB];
// per-split packed partial argmax: (val, idx-bits) in one u64
__device__ unsigned long long g_pack[NSPLIT][BATCH];

// ---- packed f32x2 helpers (sm_103a FFMA2 path) ----
__device__ __forceinline__ unsigned long long pack2(float lo, float hi) {
    unsigned long long r;
    asm("mov.b64 %0, {%1, %2};" : "=l"(r) : "f"(lo), "f"(hi));
    return r;
}
__device__ __forceinline__ void unpack2(unsigned long long v, float& lo, float& hi) {
    asm("mov.b64 {%0, %1}, %2;" : "=f"(lo), "=f"(hi) : "l"(v));
}
__device__ __forceinline__ unsigned long long fmul2(unsigned long long a, unsigned long long b) {
    unsigned long long d;
    asm("mul.rn.f32x2 %0, %1, %2;" : "=l"(d) : "l"(a), "l"(b));
    return d;
}
__device__ __forceinline__ unsigned long long ffma2(unsigned long long a, unsigned long long b,
                                                    unsigned long long c) {
    unsigned long long d;
    asm("fma.rn.f32x2 %0, %1, %2, %3;" : "=l"(d) : "l"(a), "l"(b), "l"(c));
    return d;
}

__device__ __forceinline__ int load_id(const void* p, int i, int ids64) {
    return ids64 ? (int)((const long long*)p)[i] : ((const int*)p)[i];
}

// ---- MLP kernel (detect fused): one sample per thread ----
// Per-CTA id-layout detection from 256 sampled u64-slots:
//   int64 ids  => all odd 32-bit words zero (ids < 2490). P[false int32->int64] ~ 0.
//   project_ids have max >= 1807 among 256 samples with P ~ 1 - e^-82.
__global__ __launch_bounds__(256)
void mlp_kernel(const void* __restrict__ idA,
                const void* __restrict__ idB,
                const float* __restrict__ worker_emb,
                const float* __restrict__ project_emb,
                const float* __restrict__ W1,
                const float* __restrict__ b1,
                const float* __restrict__ W2,
                const float* __restrict__ b2)
{
    __shared__ float sW1[HIDDEN * STATE_DIM];
    __shared__ float sb1[HIDDEN];
    __shared__ float sW2[EMB * HIDDEN];
    __shared__ float sb2[EMB];
    __shared__ unsigned int s_or[8], s_mx[8];
    __shared__ int s_swap, s_ids64;

    const int tid = threadIdx.x;

    // -- fused detection (parallel with weight staging) --
    {
        const unsigned int* a32 = (const unsigned int*)idA;
        const unsigned int* b32 = (const unsigned int*)idB;
        const int i = tid * (BATCH / 512);              // 256 sampled u64-slots
        unsigned int odd_or  = a32[2 * i + 1] | b32[2 * i + 1];
        unsigned int even_mx = a32[2 * i];
        #pragma unroll
        for (int o = 16; o > 0; o >>= 1) {
            odd_or  |= __shfl_xor_sync(0xffffffffu, odd_or, o);
            even_mx  = max(even_mx, __shfl_xor_sync(0xffffffffu, even_mx, o));
        }
        if ((tid & 31) == 0) { s_or[tid >> 5] = odd_or; s_mx[tid >> 5] = even_mx; }
    }

    for (int i = tid; i < HIDDEN * STATE_DIM; i += 256) sW1[i] = W1[i];
    for (int i = tid; i < EMB * HIDDEN; i += 256)       sW2[i] = W2[i];
    if (tid < HIDDEN) sb1[tid] = b1[tid];
    if (tid < EMB)    sb2[tid] = b2[tid];
    __syncthreads();

    if (tid == 0) {
        unsigned int oo = 0, mm = 0;
        #pragma unroll
        for (int w = 0; w < 8; w++) { oo |= s_or[w]; mm = max(mm, s_mx[w]); }
        s_ids64 = (oo == 0) ? 1 : 0;
        s_swap  = (mm >= (unsigned)N_WORKER) ? 1 : 0;
    }
    __syncthreads();

    const int swap  = s_swap;
    const int ids64 = s_ids64;
    const void* worker_ids  = swap ? idB : idA;
    const void* project_ids = swap ? idA : idB;

    const int g  = blockIdx.x * 256 + tid;
    const int wi = load_id(worker_ids,  g, ids64);
    const int pi = load_id(project_ids, g, ids64);

    float x[STATE_DIM];
    const float* wrow = worker_emb + wi * EMB;
    const float* prow = project_emb + pi * EMB;
    #pragma unroll
    for (int j = 0; j < EMB; j++) x[j] = __ldg(wrow + j);
    #pragma unroll
    for (int j = 0; j < EMB; j++) x[EMB + j] = __ldg(prow + j);

    float a[EMB];
    #pragma unroll
    for (int d = 0; d < EMB; d++) a[d] = sb2[d];

    #pragma unroll 2
    for (int k = 0; k < HIDDEN; k++) {
        float hk = sb1[k];
        #pragma unroll
        for (int j = 0; j < STATE_DIM; j++) hk += sW1[k * STATE_DIM + j] * x[j];
        hk = fmaxf(hk, 0.0f);
        #pragma unroll
        for (int d = 0; d < EMB; d++) a[d] += sW2[d * HIDDEN + k] * hk;
    }
    // g_w row is 40B -> 8-byte aligned: 5 STG.64
    float2* wrow_out = reinterpret_cast<float2*>(g_w[g]);
    #pragma unroll
    for (int j = 0; j < 5; j++) wrow_out[j] = make_float2(a[2 * j], a[2 * j + 1]);
}

// ---- actor: sample-pair packed dots; 4 samples/thread; 16 warps/SM ----
__global__ __launch_bounds__(THREADS, 4)
void actor_kernel(const float* __restrict__ project_emb)
{
    // duplicated-pair table: tbl[c*10 + j] = (t_c[j], t_c[j]); 15360 B
    __shared__ __align__(16) unsigned long long tbl[SPLIT_CAND * EMB];

    const int split = blockIdx.x % NSPLIT;
    const int sblk  = blockIdx.x / NSPLIT;
    const int c0    = split * SPLIT_CAND;     // global candidate base
    const int tid   = threadIdx.x;

    // stage duplicated pairs; NaN pad beyond NCAND (NaN never wins '>')
    for (int e = tid; e < SPLIT_CAND * EMB; e += THREADS) {
        const int c = e / EMB;
        const int j = e - c * EMB;
        const int ci = c0 + c;
        const float t = (ci < NCAND) ? __ldg(project_emb + (ci + 1) * EMB + j)
                                     : __int_as_float(0x7fffffff);
        tbl[e] = pack2(t, t);
    }

    // per-thread: 4 samples -> 2 sample-pair packed weight vectors (40 regs)
    int g[SPT];
    unsigned long long wd01[EMB], wd23[EMB];
    {
        float aw[SPT][EMB];
        #pragma unroll
        for (int s = 0; s < SPT; s++) {
            g[s] = (sblk * SPT + s) * THREADS + tid;
            const float2* wr = reinterpret_cast<const float2*>(g_w[g[s]]);
            #pragma unroll
            for (int j = 0; j < 5; j++) {
                const float2 v = __ldg(wr + j);
                aw[s][2 * j] = v.x; aw[s][2 * j + 1] = v.y;
            }
        }
        #pragma unroll
        for (int j = 0; j < EMB; j++) {
            wd01[j] = pack2(aw[0][j], aw[1][j]);
            wd23[j] = pack2(aw[2][j], aw[3][j]);
        }
    }
    __syncthreads();

    float bv[SPT];
    int   bc[SPT];
    #pragma unroll
    for (int s = 0; s < SPT; s++) { bv[s] = __int_as_float(0xff800000); bc[s] = 0; }

    const ulonglong2* q = reinterpret_cast<const ulonglong2*>(tbl);
    #pragma unroll 2
    for (int c = 0; c < SPLIT_CAND; c++) {
        const ulonglong2 q0 = q[c * 5 + 0];   // dims 0,1 (each duplicated)
        const ulonglong2 q1 = q[c * 5 + 1];   // dims 2,3
        const ulonglong2 q2 = q[c * 5 + 2];   // dims 4,5
        const ulonglong2 q3 = q[c * 5 + 3];   // dims 6,7
        const ulonglong2 q4 = q[c * 5 + 4];   // dims 8,9

        unsigned long long a01 = fmul2(wd01[0], q0.x);
        unsigned long long a23 = fmul2(wd23[0], q0.x);
        a01 = ffma2(wd01[1], q0.y, a01);  a23 = ffma2(wd23[1], q0.y, a23);
        a01 = ffma2(wd01[2], q1.x, a01);  a23 = ffma2(wd23[2], q1.x, a23);
        a01 = ffma2(wd01[3], q1.y, a01);  a23 = ffma2(wd23[3], q1.y, a23);
        a01 = ffma2(wd01[4], q2.x, a01);  a23 = ffma2(wd23[4], q2.x, a23);
        a01 = ffma2(wd01[5], q2.y, a01);  a23 = ffma2(wd23[5], q2.y, a23);
        a01 = ffma2(wd01[6], q3.x, a01);  a23 = ffma2(wd23[6], q3.x, a23);
        a01 = ffma2(wd01[7], q3.y, a01);  a23 = ffma2(wd23[7], q3.y, a23);
        a01 = ffma2(wd01[8], q4.x, a01);  a23 = ffma2(wd23[8], q4.x, a23);
        a01 = ffma2(wd01[9], q4.y, a01);  a23 = ffma2(wd23[9], q4.y, a23);

        float d[SPT];
        unpack2(a01, d[0], d[1]);
        unpack2(a23, d[2], d[3]);
        #pragma unroll
        for (int s = 0; s < SPT; s++) {
            const bool gt = (d[s] > bv[s]);   // ascending c + strict '>' = first max
            bv[s] = gt ? d[s] : bv[s];
            bc[s] = gt ? c    : bc[s];
        }
    }

    #pragma unroll
    for (int s = 0; s < SPT; s++)
        g_pack[split][g[s]] = pack2(bv[s], __int_as_float(c0 + bc[s]));
}

// ---- merge the 13 splits; splits ascend in index: strict '>' keeps first max ----
__global__ void merge_kernel(float* __restrict__ out)
{
    const int i = blockIdx.x * 256 + threadIdx.x;
    float v, ixf;
    unpack2(g_pack[0][i], v, ixf);
    #pragma unroll
    for (int s = 1; s < NSPLIT; s++) {
        float vs, ixs;
        unpack2(g_pack[s][i], vs, ixs);
        const bool t = (vs > v);
        v   = t ? vs  : v;
        ixf = t ? ixs : ixf;
    }
    out[i] = (float)(__float_as_int(ixf) + 1);
}

extern "C" void kernel_launch(void* const* d_in, const int* in_sizes, int n_in,
                              void* d_out, int out_size)
{
    // Order-proof binding: every float array has a unique element count.
    const void*  idA = nullptr;
    const void*  idB = nullptr;
    const float* worker_emb  = nullptr;  // 18070
    const float* project_emb = nullptr;  // 24900
    const float* W1 = nullptr;           // 800
    const float* b1 = nullptr;           // 40
    const float* W2 = nullptr;           // 400
    const float* b2 = nullptr;           // 10

    for (int i = 0; i < n_in; i++) {
        switch (in_sizes[i]) {
            case BATCH: if (!idA) idA = d_in[i];
                        else      idB = d_in[i];                      break;
            case 18070: worker_emb  = (const float*)d_in[i];          break;
            case 24900: project_emb = (const float*)d_in[i];          break;
            case 800:   W1 = (const float*)d_in[i];                   break;
            case 40:    b1 = (const float*)d_in[i];                   break;
            case 400:   W2 = (const float*)d_in[i];                   break;
            case 10:    b2 = (const float*)d_in[i];                   break;
            default: break;
        }
    }

    mlp_kernel<<<BATCH / 256, 256>>>(idA, idB, worker_emb, project_emb,
                                     W1, b1, W2, b2);
    actor_kernel<<<ACTOR_CTAS, THREADS>>>(project_emb);
    merge_kernel<<<BATCH / 256, 256>>>((float*)d_out);
}